// round 2
// baseline (speedup 1.0000x reference)
#include <cuda_runtime.h>
#include <cuda_bf16.h>
#include <cstdint>

#define BB 8192
#define DD 1024

// ---------------- scratch (device globals: no allocations allowed) -------------
__device__ __align__(16) __nv_bfloat16 g_qn[BB * DD];   // 16 MB
__device__ __align__(16) __nv_bfloat16 g_pn[BB * DD];   // 16 MB
__device__ float g_mse[BB];
__device__ float g_rowloss[BB];

// =======================================================================
// Stage 1: per-row norms, MSE partials, normalized bf16 writes.
// One warp per row (q row + p row). grid = 1024, block = 256.
// =======================================================================
__global__ void __launch_bounds__(256) prep_kernel(const float* __restrict__ sq,
                                                   const float* __restrict__ sp,
                                                   const float* __restrict__ tq,
                                                   const float* __restrict__ tp)
{
    const int lane = threadIdx.x & 31;
    const int wid  = threadIdx.x >> 5;
    const int row  = blockIdx.x * 8 + wid;

    const float4* q4  = (const float4*)(sq + (size_t)row * DD);
    const float4* p4  = (const float4*)(sp + (size_t)row * DD);
    const float4* tq4 = (const float4*)(tq + (size_t)row * DD);
    const float4* tp4 = (const float4*)(tp + (size_t)row * DD);

    float4 qa[8], pa[8];
    float nq = 0.f, np_ = 0.f, mse = 0.f;
#pragma unroll
    for (int i = 0; i < 8; ++i) {
        float4 a = q4[i * 32 + lane]; qa[i] = a;
        float4 t = tq4[i * 32 + lane];
        nq += a.x * a.x + a.y * a.y + a.z * a.z + a.w * a.w;
        float dx = a.x - t.x, dy = a.y - t.y, dz = a.z - t.z, dw = a.w - t.w;
        mse += dx * dx + dy * dy + dz * dz + dw * dw;
    }
#pragma unroll
    for (int i = 0; i < 8; ++i) {
        float4 a = p4[i * 32 + lane]; pa[i] = a;
        float4 t = tp4[i * 32 + lane];
        np_ += a.x * a.x + a.y * a.y + a.z * a.z + a.w * a.w;
        float dx = a.x - t.x, dy = a.y - t.y, dz = a.z - t.z, dw = a.w - t.w;
        mse += dx * dx + dy * dy + dz * dz + dw * dw;
    }
#pragma unroll
    for (int off = 16; off; off >>= 1) {
        nq  += __shfl_xor_sync(0xffffffffu, nq,  off);
        np_ += __shfl_xor_sync(0xffffffffu, np_, off);
        mse += __shfl_xor_sync(0xffffffffu, mse, off);
    }
    const float invq = 1.f / fmaxf(sqrtf(nq),  1e-8f);
    const float invp = 1.f / fmaxf(sqrtf(np_), 1e-8f);

    __nv_bfloat162* qd = (__nv_bfloat162*)(g_qn + (size_t)row * DD);
    __nv_bfloat162* pd = (__nv_bfloat162*)(g_pn + (size_t)row * DD);
#pragma unroll
    for (int i = 0; i < 8; ++i) {
        int idx = (i * 32 + lane) * 2;
        qd[idx]     = __float22bfloat162_rn(make_float2(qa[i].x * invq, qa[i].y * invq));
        qd[idx + 1] = __float22bfloat162_rn(make_float2(qa[i].z * invq, qa[i].w * invq));
        pd[idx]     = __float22bfloat162_rn(make_float2(pa[i].x * invp, pa[i].y * invp));
        pd[idx + 1] = __float22bfloat162_rn(make_float2(pa[i].z * invp, pa[i].w * invp));
    }
    if (lane == 0) g_mse[row] = mse;
}

// =======================================================================
// Stage 2: fused bf16 GEMM (q·p^T) + streaming sum-exp + diagonal capture.
// CTA: 64 rows (q pinned in smem), streams p in 64x128 bf16 chunks via
// 4-stage cp.async pipeline. 256 threads = 8 warps (4 rowgroups x 2 colhalves).
// Logits never hit memory. No max-tracking needed: |logit| <= ~1.
// =======================================================================
#define QROW_BYTES   2064                 // (1024 + 8 pad) bf16
#define Q_BYTES      (64 * QROW_BYTES)    // 132096
#define BROW_BYTES   272                  // (128 + 8 pad) bf16
#define BCHUNK_BYTES (64 * BROW_BYTES)    // 17408
#define NSTG         4
#define RED_OFF      (Q_BYTES + NSTG * BCHUNK_BYTES)  // 201728
#define SMEM_SZ      (RED_OFF + 256 * 4)              // 202752
#define NITER        1024                 // 128 jtiles * 8 kchunks

__device__ __forceinline__ void cp16(uint32_t dst, const void* src)
{
    asm volatile("cp.async.cg.shared.global [%0], [%1], 16;" :: "r"(dst), "l"(src));
}
__device__ __forceinline__ void cp_commit() { asm volatile("cp.async.commit_group;"); }

__global__ void __launch_bounds__(256, 1) lse_kernel()
{
    extern __shared__ char smem[];
    const int tid  = threadIdx.x;
    const int lane = tid & 31;
    const int wid  = tid >> 5;
    const int blk  = blockIdx.x;

    const uint32_t smem_u32 = (uint32_t)__cvta_generic_to_shared(smem);
    const uint32_t qbase    = smem_u32;
    const uint32_t bbase    = smem_u32 + Q_BYTES;
    float* red = (float*)(smem + RED_OFF);

    // ---- load the 64-row q tile (row-major, padded rows) ----
    {
        const uint4* qsrc = (const uint4*)(g_qn + (size_t)blk * 64 * DD);
#pragma unroll
        for (int i = 0; i < 32; ++i) {
            int flat = tid + i * 256;        // 0..8191  (64 rows x 128 16B-chunks)
            int r = flat >> 7, c = flat & 127;
            *(uint4*)(smem + r * QROW_BYTES + c * 16) = qsrc[flat];
        }
    }

    // ---- cp.async chunk issuer: chunk it -> (jtile, kchunk) ----
    auto issue_chunk = [&](int it) {
        if (it < NITER) {
            int jt = it >> 3, kc = it & 7;
            const char* src = (const char*)g_pn + ((size_t)jt * 64 * DD + kc * 128) * 2;
            uint32_t dst = bbase + (it & 3) * BCHUNK_BYTES;
#pragma unroll
            for (int i = 0; i < 4; ++i) {
                int flat = tid + i * 256;     // 0..1023 (64 rows x 16 16B-chunks)
                int r = flat >> 4, cs = flat & 15;
                cp16(dst + r * BROW_BYTES + cs * 16, src + r * 2048 + cs * 16);
            }
        }
        cp_commit();
    };
    issue_chunk(0); issue_chunk(1); issue_chunk(2);

    const int rg  = wid >> 1;     // rowgroup (16 rows)
    const int ch  = wid & 1;      // column half (32 cols)
    const int gid = lane >> 2;
    const int qid = lane & 3;
    const int R0  = blk * 64 + rg * 16 + gid;   // global row for c0/c1 (c2/c3: R0+8)

    float s0 = 0.f, s1 = 0.f, d0 = 0.f, d1 = 0.f;
    float acc[4][4];

    // ldmatrix address invariants
    const uint32_t a_row_addr = qbase + (rg * 16 + (lane & 15)) * QROW_BYTES
                              + ((lane >> 4) << 4);
    const uint32_t b_row_off  = (ch * 32 + (lane & 7) + ((lane >> 4) << 3)) * BROW_BYTES
                              + (((lane >> 3) & 1) << 4);

    for (int it = 0; it < NITER; ++it) {
        const int jt = it >> 3, kc = it & 7;
        if (kc == 0) {
#pragma unroll
            for (int n = 0; n < 4; ++n)
#pragma unroll
                for (int e = 0; e < 4; ++e) acc[n][e] = 0.f;
        }

        asm volatile("cp.async.wait_group 2;" ::: "memory");
        __syncthreads();

        const uint32_t bch = bbase + (it & 3) * BCHUNK_BYTES;
#pragma unroll
        for (int ks = 0; ks < 8; ++ks) {
            uint32_t a0, a1, a2, a3;
            uint32_t aaddr = a_row_addr + kc * 256 + ks * 32;
            asm volatile("ldmatrix.sync.aligned.m8n8.x4.shared.b16 {%0,%1,%2,%3}, [%4];"
                         : "=r"(a0), "=r"(a1), "=r"(a2), "=r"(a3) : "r"(aaddr));
#pragma unroll
            for (int h = 0; h < 2; ++h) {
                uint32_t b0, b1, b2, b3;
                uint32_t baddr = bch + b_row_off + h * (16 * BROW_BYTES) + ks * 32;
                asm volatile("ldmatrix.sync.aligned.m8n8.x4.shared.b16 {%0,%1,%2,%3}, [%4];"
                             : "=r"(b0), "=r"(b1), "=r"(b2), "=r"(b3) : "r"(baddr));
                asm volatile("mma.sync.aligned.m16n8k16.row.col.f32.bf16.bf16.f32 "
                             "{%0,%1,%2,%3}, {%4,%5,%6,%7}, {%8,%9}, {%0,%1,%2,%3};"
                             : "+f"(acc[2*h][0]), "+f"(acc[2*h][1]), "+f"(acc[2*h][2]), "+f"(acc[2*h][3])
                             : "r"(a0), "r"(a1), "r"(a2), "r"(a3), "r"(b0), "r"(b1));
                asm volatile("mma.sync.aligned.m16n8k16.row.col.f32.bf16.bf16.f32 "
                             "{%0,%1,%2,%3}, {%4,%5,%6,%7}, {%8,%9}, {%0,%1,%2,%3};"
                             : "+f"(acc[2*h+1][0]), "+f"(acc[2*h+1][1]), "+f"(acc[2*h+1][2]), "+f"(acc[2*h+1][3])
                             : "r"(a0), "r"(a1), "r"(a2), "r"(a3), "r"(b2), "r"(b3));
            }
        }
        issue_chunk(it + 3);

        if (kc == 7) {  // jtile complete: fold logits into streaming sum-exp
#pragma unroll
            for (int nt = 0; nt < 4; ++nt) {
                const int C = jt * 64 + ch * 32 + nt * 8 + qid * 2;
                const float v0 = acc[nt][0], v1 = acc[nt][1];
                const float v2 = acc[nt][2], v3 = acc[nt][3];
                s0 += __expf(v0) + __expf(v1);
                s1 += __expf(v2) + __expf(v3);
                if (C     == R0    ) d0 = v0;
                if (C + 1 == R0    ) d0 = v1;
                if (C     == R0 + 8) d1 = v2;
                if (C + 1 == R0 + 8) d1 = v3;
            }
        }
    }

    // ---- reduce across the 4 lanes sharing each row ----
#pragma unroll
    for (int off = 1; off < 4; off <<= 1) {
        s0 += __shfl_xor_sync(0xffffffffu, s0, off);
        s1 += __shfl_xor_sync(0xffffffffu, s1, off);
        d0 += __shfl_xor_sync(0xffffffffu, d0, off);
        d1 += __shfl_xor_sync(0xffffffffu, d1, off);
    }
    if (qid == 0) {
        const int lr = rg * 16 + gid;
        red[ch * 64 + lr]           = s0;
        red[ch * 64 + lr + 8]       = s1;
        red[128 + ch * 64 + lr]     = d0;
        red[128 + ch * 64 + lr + 8] = d1;
    }
    __syncthreads();
    if (tid < 64) {
        const float S  = red[tid]       + red[64 + tid];
        const float Dg = red[128 + tid] + red[192 + tid];
        g_rowloss[blk * 64 + tid] = __logf(S) - Dg;
    }
}

// =======================================================================
// Stage 3: final scalar.
// loss = 0.5 * [ mse_total/(2*B*D) ] + 0.5 * [ rowloss_sum/B ]
// =======================================================================
__global__ void __launch_bounds__(256) finalize_kernel(float* __restrict__ out)
{
    __shared__ float sa[256], sb[256];
    float a = 0.f, b = 0.f;
    for (int i = threadIdx.x; i < BB; i += 256) {
        a += g_mse[i];
        b += g_rowloss[i];
    }
    sa[threadIdx.x] = a; sb[threadIdx.x] = b;
    __syncthreads();
    for (int off = 128; off; off >>= 1) {
        if (threadIdx.x < off) {
            sa[threadIdx.x] += sa[threadIdx.x + off];
            sb[threadIdx.x] += sb[threadIdx.x + off];
        }
        __syncthreads();
    }
    if (threadIdx.x == 0) {
        const float distill   = sa[0] / (2.f * (float)BB * (float)DD);
        const float retrieval = sb[0] / (float)BB;
        out[0] = 0.5f * distill + 0.5f * retrieval;
    }
}

// =======================================================================
extern "C" void kernel_launch(void* const* d_in, const int* in_sizes, int n_in,
                              void* d_out, int out_size)
{
    (void)in_sizes; (void)n_in; (void)out_size;
    const float* sq = (const float*)d_in[0];
    const float* sp = (const float*)d_in[1];
    const float* tq = (const float*)d_in[2];
    const float* tp = (const float*)d_in[3];

    cudaFuncSetAttribute(lse_kernel, cudaFuncAttributeMaxDynamicSharedMemorySize, SMEM_SZ);

    prep_kernel<<<BB / 8, 256>>>(sq, sp, tq, tp);
    lse_kernel<<<BB / 64, 256, SMEM_SZ>>>();
    finalize_kernel<<<1, 256>>>((float*)d_out);
}

// round 4
// speedup vs baseline: 1.6136x; 1.6136x over previous
#include <cuda_runtime.h>
#include <cuda_bf16.h>
#include <cstdint>

#define BB 8192
#define DD 1024

// ---------------- scratch (device globals: no allocations allowed) -------------
__device__ __align__(16) uint8_t g_q8[BB * DD];   // 8 MB, e4m3, rows scaled x16
__device__ __align__(16) uint8_t g_p8[BB * DD];   // 8 MB
__device__ float g_mse[BB];
__device__ float g_sumexp[BB];
__device__ float g_diag[BB];

// =======================================================================
// Stage 1: per-row norms, MSE partials, fp8(e4m3) normalized writes (x16).
// One warp per row-pair. grid = 1024, block = 256. Also zeroes g_sumexp.
// =======================================================================
__device__ __forceinline__ uint32_t pack_e4m3x4(float x0, float x1, float x2, float x3)
{
    uint32_t w;
    asm("{\n\t.reg .b16 lo, hi;\n\t"
        "cvt.rn.satfinite.e4m3x2.f32 lo, %2, %1;\n\t"
        "cvt.rn.satfinite.e4m3x2.f32 hi, %4, %3;\n\t"
        "mov.b32 %0, {lo, hi};\n\t}"
        : "=r"(w) : "f"(x0), "f"(x1), "f"(x2), "f"(x3));
    return w;
}

__global__ void __launch_bounds__(256) prep_kernel(const float* __restrict__ sq,
                                                   const float* __restrict__ sp,
                                                   const float* __restrict__ tq,
                                                   const float* __restrict__ tp)
{
    if (blockIdx.x < 32) g_sumexp[blockIdx.x * 256 + threadIdx.x] = 0.f;

    const int lane = threadIdx.x & 31;
    const int wid  = threadIdx.x >> 5;
    const int row  = blockIdx.x * 8 + wid;

    const float4* q4  = (const float4*)(sq + (size_t)row * DD);
    const float4* p4  = (const float4*)(sp + (size_t)row * DD);
    const float4* tq4 = (const float4*)(tq + (size_t)row * DD);
    const float4* tp4 = (const float4*)(tp + (size_t)row * DD);

    float4 qa[8], pa[8];
    float nq = 0.f, np_ = 0.f, mse = 0.f;
#pragma unroll
    for (int i = 0; i < 8; ++i) {
        float4 a = q4[i * 32 + lane]; qa[i] = a;
        float4 t = tq4[i * 32 + lane];
        nq += a.x * a.x + a.y * a.y + a.z * a.z + a.w * a.w;
        float dx = a.x - t.x, dy = a.y - t.y, dz = a.z - t.z, dw = a.w - t.w;
        mse += dx * dx + dy * dy + dz * dz + dw * dw;
    }
#pragma unroll
    for (int i = 0; i < 8; ++i) {
        float4 a = p4[i * 32 + lane]; pa[i] = a;
        float4 t = tp4[i * 32 + lane];
        np_ += a.x * a.x + a.y * a.y + a.z * a.z + a.w * a.w;
        float dx = a.x - t.x, dy = a.y - t.y, dz = a.z - t.z, dw = a.w - t.w;
        mse += dx * dx + dy * dy + dz * dz + dw * dw;
    }
#pragma unroll
    for (int off = 16; off; off >>= 1) {
        nq  += __shfl_xor_sync(0xffffffffu, nq,  off);
        np_ += __shfl_xor_sync(0xffffffffu, np_, off);
        mse += __shfl_xor_sync(0xffffffffu, mse, off);
    }
    // scale by 16 so e4m3 values sit in normal range (std ~0.5)
    const float invq = 16.f / fmaxf(sqrtf(nq),  1e-8f);
    const float invp = 16.f / fmaxf(sqrtf(np_), 1e-8f);

    uint32_t* qd = (uint32_t*)(g_q8 + (size_t)row * DD);
    uint32_t* pd = (uint32_t*)(g_p8 + (size_t)row * DD);
#pragma unroll
    for (int i = 0; i < 8; ++i) {
        int idx = i * 32 + lane;
        qd[idx] = pack_e4m3x4(qa[i].x * invq, qa[i].y * invq, qa[i].z * invq, qa[i].w * invq);
        pd[idx] = pack_e4m3x4(pa[i].x * invp, pa[i].y * invp, pa[i].z * invp, pa[i].w * invp);
    }
    if (lane == 0) g_mse[row] = mse;
}

// =======================================================================
// Stage 2: fp8 e4m3 mma.sync GEMM (128x128 tile/CTA) + FMA-poly exp-sum.
// grid = 64x64 = 4096 CTAs, 256 thr = 8 warps (2 warp-rows x 4 warp-cols),
// warp tile 64x32. K=1024B streamed in 8 chunks of 128B, 3-stage cp.async.
// Logits never hit memory; exp via degree-8 Horner (no MUFU).
// =======================================================================
#define NSTG        3
#define STAGE_BYTES 32768   // A 128x128B + B 128x128B
#define SUMS_OFF    (NSTG * STAGE_BYTES)
#define SMEM_SZ     (1024 + NSTG * STAGE_BYTES + 2048)

__device__ __forceinline__ void cp16(uint32_t dst, const void* src)
{
    asm volatile("cp.async.cg.shared.global [%0], [%1], 16;" :: "r"(dst), "l"(src));
}
__device__ __forceinline__ void cp_commit() { asm volatile("cp.async.commit_group;"); }

__device__ __forceinline__ void ldsm4(uint32_t* r, uint32_t addr)
{
    asm volatile("ldmatrix.sync.aligned.m8n8.x4.shared.b16 {%0,%1,%2,%3}, [%4];"
                 : "=r"(r[0]), "=r"(r[1]), "=r"(r[2]), "=r"(r[3]) : "r"(addr));
}

__device__ __forceinline__ void mma8(float* d, const uint32_t* a, uint32_t b0, uint32_t b1)
{
    asm volatile("mma.sync.aligned.m16n8k32.row.col.f32.e4m3.e4m3.f32 "
                 "{%0,%1,%2,%3}, {%4,%5,%6,%7}, {%8,%9}, {%0,%1,%2,%3};"
                 : "+f"(d[0]), "+f"(d[1]), "+f"(d[2]), "+f"(d[3])
                 : "r"(a[0]), "r"(a[1]), "r"(a[2]), "r"(a[3]), "r"(b0), "r"(b1));
}

// exp(x) on [-1.05, 1.05]: degree-8 Taylor (Horner), worst rel err ~3e-5
__device__ __forceinline__ float exp_poly(float x)
{
    float p = 2.4801587e-5f;
    p = fmaf(p, x, 1.9841270e-4f);
    p = fmaf(p, x, 1.3888889e-3f);
    p = fmaf(p, x, 8.3333333e-3f);
    p = fmaf(p, x, 4.1666667e-2f);
    p = fmaf(p, x, 1.6666667e-1f);
    p = fmaf(p, x, 0.5f);
    p = fmaf(p, x, 1.0f);
    p = fmaf(p, x, 1.0f);
    return p;
}

__global__ void __launch_bounds__(256, 2) lse_kernel()
{
    extern __shared__ char smem[];
    const int tid  = threadIdx.x;
    const int lane = tid & 31;
    const int wid  = tid >> 5;
    const int rb   = blockIdx.x & 63;
    const int cb   = blockIdx.x >> 6;
    const int wr   = wid >> 2;      // warp-row: rows wr*64..+63
    const int wc   = wid & 3;       // warp-col: cols wc*32..+31
    const int gid  = lane >> 2;
    const int qid  = lane & 3;

    const uint32_t sb   = (uint32_t)__cvta_generic_to_shared(smem);
    const uint32_t stg0 = (sb + 1023u) & ~1023u;
    float* sums = (float*)(smem + (stg0 - sb) + SUMS_OFF);   // [128][4]

    const char* Abase = (const char*)g_q8 + (size_t)rb * 128 * DD;
    const char* Bbase = (const char*)g_p8 + (size_t)cb * 128 * DD;

    // chunk cc: A[128 x 128B] + B[128 x 128B], XOR-swizzled 16B lanes
    auto load_chunk = [&](int cc) {
        if (cc < 8) {
            uint32_t stg = stg0 + (uint32_t)(cc % NSTG) * STAGE_BYTES;
#pragma unroll
            for (int i = 0; i < 8; ++i) {
                int flat = tid + i * 256;          // 0..2047
                int isB  = flat >> 10;
                int f    = flat & 1023;
                int r    = f >> 3, c16 = f & 7;
                uint32_t dst = stg + (uint32_t)(isB << 14)
                             + (uint32_t)(r * 128 + ((c16 ^ (r & 7)) << 4));
                const char* src = (isB ? Bbase : Abase) + (size_t)r * DD + cc * 128 + c16 * 16;
                cp16(dst, src);
            }
        }
        cp_commit();
    };
    load_chunk(0); load_chunk(1); load_chunk(2);

    float acc[4][4][4];
#pragma unroll
    for (int mt = 0; mt < 4; ++mt)
#pragma unroll
        for (int nt = 0; nt < 4; ++nt)
#pragma unroll
            for (int e = 0; e < 4; ++e) acc[mt][nt][e] = 0.f;

    // ldmatrix lane->address invariants (identical mapping to round-1, proven)
    const int arow = wr * 64 + (lane & 15);                    // + mt*16
    const int aseg = lane >> 4;
    const int brow = wc * 32 + (lane & 7) + ((lane >> 4) << 3); // + pr*16
    const int bseg = (lane >> 3) & 1;

    for (int c = 0; c < 8; ++c) {
        asm volatile("cp.async.wait_group 2;" ::: "memory");
        __syncthreads();

        const uint32_t stgA = stg0 + (uint32_t)(c % NSTG) * STAGE_BYTES;
        const uint32_t stgB = stgA + 16384;
#pragma unroll
        for (int ks = 0; ks < 4; ++ks) {
            uint32_t a[4][4];
#pragma unroll
            for (int mt = 0; mt < 4; ++mt) {
                int r = arow + mt * 16;
                ldsm4(a[mt], stgA + r * 128 + (((ks * 2 + aseg) ^ (r & 7)) << 4));
            }
#pragma unroll
            for (int pr = 0; pr < 2; ++pr) {
                int r = brow + pr * 16;
                uint32_t b[4];
                ldsm4(b, stgB + r * 128 + (((ks * 2 + bseg) ^ (r & 7)) << 4));
#pragma unroll
                for (int mt = 0; mt < 4; ++mt) {
                    mma8(acc[mt][2 * pr],     a[mt], b[0], b[1]);
                    mma8(acc[mt][2 * pr + 1], a[mt], b[2], b[3]);
                }
            }
        }
        __syncthreads();          // all warps done with stage c before overwrite
        load_chunk(c + 3);
    }

    // ---- epilogue: unscale (x16*x16 -> /256), poly-exp, reduce, diagonal ----
    const float INV = 1.0f / 256.0f;
    float rsum[4][2];
#pragma unroll
    for (int mt = 0; mt < 4; ++mt) { rsum[mt][0] = 0.f; rsum[mt][1] = 0.f; }

#pragma unroll
    for (int mt = 0; mt < 4; ++mt)
#pragma unroll
        for (int nt = 0; nt < 4; ++nt)
#pragma unroll
            for (int e = 0; e < 4; ++e) {
                const float x = acc[mt][nt][e] * INV;
                rsum[mt][e >> 1] += exp_poly(x);
                const int rg = rb * 128 + wr * 64 + mt * 16 + gid + ((e >> 1) << 3);
                const int cg = cb * 128 + wc * 32 + nt * 8 + qid * 2 + (e & 1);
                if (rg == cg) g_diag[rg] = x;
            }

#pragma unroll
    for (int off = 1; off < 4; off <<= 1)
#pragma unroll
        for (int mt = 0; mt < 4; ++mt) {
            rsum[mt][0] += __shfl_xor_sync(0xffffffffu, rsum[mt][0], off);
            rsum[mt][1] += __shfl_xor_sync(0xffffffffu, rsum[mt][1], off);
        }
    if (qid == 0) {
#pragma unroll
        for (int mt = 0; mt < 4; ++mt) {
            sums[(wr * 64 + mt * 16 + gid) * 4 + wc]     = rsum[mt][0];
            sums[(wr * 64 + mt * 16 + gid + 8) * 4 + wc] = rsum[mt][1];
        }
    }
    __syncthreads();
    if (tid < 128) {
        const float t = sums[tid * 4] + sums[tid * 4 + 1]
                      + sums[tid * 4 + 2] + sums[tid * 4 + 3];
        atomicAdd(&g_sumexp[rb * 128 + tid], t);
    }
}

// =======================================================================
// Stage 3: final scalar.
// loss = 0.5 * [ mse_total/(2*B*D) ] + 0.5 * mean( log(sumexp) - diag )
// =======================================================================
__global__ void __launch_bounds__(256) finalize_kernel(float* __restrict__ out)
{
    __shared__ float sa[256], sb_[256];
    float a = 0.f, b = 0.f;
    for (int i = threadIdx.x; i < BB; i += 256) {
        a += g_mse[i];
        b += __logf(g_sumexp[i]) - g_diag[i];
    }
    sa[threadIdx.x] = a; sb_[threadIdx.x] = b;
    __syncthreads();
    for (int off = 128; off; off >>= 1) {
        if (threadIdx.x < off) {
            sa[threadIdx.x]  += sa[threadIdx.x + off];
            sb_[threadIdx.x] += sb_[threadIdx.x + off];
        }
        __syncthreads();
    }
    if (threadIdx.x == 0) {
        const float distill   = sa[0] / (2.f * (float)BB * (float)DD);
        const float retrieval = sb_[0] / (float)BB;
        out[0] = 0.5f * distill + 0.5f * retrieval;
    }
}

// =======================================================================
extern "C" void kernel_launch(void* const* d_in, const int* in_sizes, int n_in,
                              void* d_out, int out_size)
{
    (void)in_sizes; (void)n_in; (void)out_size;
    const float* sq = (const float*)d_in[0];
    const float* sp = (const float*)d_in[1];
    const float* tq = (const float*)d_in[2];
    const float* tp = (const float*)d_in[3];

    cudaFuncSetAttribute(lse_kernel, cudaFuncAttributeMaxDynamicSharedMemorySize, SMEM_SZ);

    prep_kernel<<<BB / 8, 256>>>(sq, sp, tq, tp);
    lse_kernel<<<4096, 256, SMEM_SZ>>>();
    finalize_kernel<<<1, 256>>>((float*)d_out);
}